// round 6
// baseline (speedup 1.0000x reference)
#include <cuda_runtime.h>
#include <cuda_fp16.h>
#include <cstdint>

#define T_TOT 65536
#define KTAPS 12              // taps kept; truncation ~0.32^12 ≈ 1e-6 rel
#define KDIM  (KTAPS * 32)    // 384
#define NCHUNK (KDIM / 64)    // 6
#define T0    24              // exact sequential steps; conv covers t in [T0+1, T_TOT]
#define NTT   512             // t-tiles of 128 rows
#define NBY   74              // CTAs per nb; 4*74 = 296 ≈ 2 waves
#define NI    7               // tiles per CTA (74*7 = 518 >= 512)

// fp16 U and fp16 B = reordered impulse response, row stride KDIM.
__device__ __half g_Uh[T_TOT * 32];
__device__ __half g_Hh[512 * KDIM];   // [o][c], c = (KTAPS-1-k)*32 + j

// ---------------------------------------------------------------------------
// helpers (baseline PTX only — nothing sm_103a-gated)
// ---------------------------------------------------------------------------
__device__ __forceinline__ uint32_t smem_u32(const void* p) {
    uint32_t a;
    asm("{ .reg .u64 t; cvta.to.shared.u64 t, %1; cvt.u32.u64 %0, t; }"
        : "=r"(a) : "l"(p));
    return a;
}
__device__ __forceinline__ void cp16(uint32_t saddr, const void* g) {
    asm volatile("cp.async.cg.shared.global [%0], [%1], 16;" :: "r"(saddr), "l"(g));
}
__device__ __forceinline__ void cp_commit() {
    asm volatile("cp.async.commit_group;" ::: "memory");
}
__device__ __forceinline__ void ldsm_x4(uint32_t* r, uint32_t addr) {
    asm volatile("ldmatrix.sync.aligned.m8n8.x4.shared.b16 {%0,%1,%2,%3}, [%4];"
                 : "=r"(r[0]), "=r"(r[1]), "=r"(r[2]), "=r"(r[3]) : "r"(addr));
}
__device__ __forceinline__ void mma16816(float* d, const uint32_t* a, const uint32_t* b) {
    asm volatile("mma.sync.aligned.m16n8k16.row.col.f32.f16.f16.f32 "
                 "{%0,%1,%2,%3}, {%4,%5,%6,%7}, {%8,%9}, {%0,%1,%2,%3};"
                 : "+f"(d[0]), "+f"(d[1]), "+f"(d[2]), "+f"(d[3])
                 : "r"(a[0]), "r"(a[1]), "r"(a[2]), "r"(a[3]), "r"(b[0]), "r"(b[1]));
}

// ---------------------------------------------------------------------------
// k_pre: blocks 0-31: impulse chains -> fp16 B matrix
//        block 32:    exact 24-step sim -> hist rows 0..24, y[0..23]
//        blocks 33+:  U -> fp16
// ---------------------------------------------------------------------------
__global__ void __launch_bounds__(256) k_pre(
    const float* __restrict__ x_nat0, const float* __restrict__ x_unnat0,
    const float* __restrict__ x_opsin0, const float* __restrict__ U,
    const float* __restrict__ A_nn, const float* __restrict__ K_nat,
    const float* __restrict__ C_y_nat, const float* __restrict__ A_uu,
    const float* __restrict__ K_un, const float* __restrict__ C_y_un,
    const float* __restrict__ Bp_nat, const float* __restrict__ Bp_un,
    const float* __restrict__ A_op, const float* __restrict__ B_op,
    const float* __restrict__ C_op, float* __restrict__ out)
{
    __shared__ float x[512], xn[512], ph[64], redn[128], redu[128];
    __shared__ float s_sn, s_su;
    const int tid = threadIdx.x;
    const int b = blockIdx.x;

    if (b >= 33) {                       // ---- U -> fp16 ----
        const int base = (b - 33) * 16384;
        #pragma unroll 4
        for (int p = 0; p < 64; p++) {
            const int idx = base + p * 256 + tid;
            g_Uh[idx] = __float2half(U[idx]);
        }
        return;
    }

    if (b < 32) {                        // ---- impulse chain for input col b ----
        const int jcol = b;
        for (int i = tid; i < 512; i += 256)
            x[i] = (i >= 256) ? B_op[(i - 256) * 32 + jcol] : 0.f;
        __syncthreads();
        for (int i = tid; i < 512; i += 256)          // tap k=0
            g_Hh[i * KDIM + (KTAPS - 1) * 32 + jcol] = __float2half(x[i]);
        for (int k = 1; k < KTAPS; k++) {
            if (tid < 128) {
                redn[tid] = C_y_nat[tid] * x[tid];
                redu[tid] = C_y_un[tid]  * x[128 + tid];
            }
            __syncthreads();
            for (int s2 = 64; s2 > 0; s2 >>= 1) {
                if (tid < s2) { redn[tid] += redn[tid + s2]; redu[tid] += redu[tid + s2]; }
                __syncthreads();
            }
            if (tid == 0) { s_sn = redn[0]; s_su = redu[0]; }
            if (tid < 64) {
                float s = 0.f;
                const float* cr = C_op + tid * 256;
                #pragma unroll 8
                for (int i2 = 0; i2 < 256; i2++) s += cr[i2] * x[256 + i2];
                ph[tid] = s;
            }
            __syncthreads();
            const float sn = s_sn, su = s_su;
            {
                const int r = tid;
                float s;
                if (r < 128) {
                    s = K_nat[r] * (sn + su);
                    const float* ar = A_nn + r * 128;
                    #pragma unroll 8
                    for (int j = 0; j < 128; j++) s += ar[j] * x[j];
                    const float* br = Bp_nat + r * 64;
                    #pragma unroll 8
                    for (int c = 0; c < 64; c++) s += br[c] * ph[c];
                } else {
                    const int rr = r - 128;
                    s = K_un[rr] * su;
                    const float* ar = A_uu + rr * 128;
                    #pragma unroll 8
                    for (int j = 0; j < 128; j++) s += ar[j] * x[128 + j];
                    const float* br = Bp_un + rr * 64;
                    #pragma unroll 8
                    for (int c = 0; c < 64; c++) s += br[c] * ph[c];
                }
                xn[r] = s;
                float so = 0.f;
                const float* ar2 = A_op + r * 256;
                #pragma unroll 8
                for (int j = 0; j < 256; j++) so += ar2[j] * x[256 + j];
                xn[256 + r] = so;
            }
            __syncthreads();
            for (int i = tid; i < 512; i += 256) {
                const float v = xn[i];
                x[i] = v;
                g_Hh[i * KDIM + (KTAPS - 1 - k) * 32 + jcol] = __float2half(v);
            }
            __syncthreads();
        }
        return;
    }

    // ---- b == 32: exact first-T0 simulation ----
    float* y_out   = out;
    float* nat_out = out + T_TOT;
    float* un_out  = nat_out + (T_TOT + 1) * 128;
    float* op_out  = un_out  + (T_TOT + 1) * 128;

    for (int i = tid; i < 512; i += 256)
        x[i] = (i < 128) ? x_nat0[i] : (i < 256) ? x_unnat0[i - 128] : x_opsin0[i - 256];
    __syncthreads();
    for (int i = tid; i < 512; i += 256) {
        const float v = x[i];
        if (i < 128)       nat_out[i] = v;
        else if (i < 256)  un_out[i - 128] = v;
        else               op_out[i - 256] = v;
    }
    for (int t = 0; t < T0; t++) {
        if (tid < 128) {
            redn[tid] = C_y_nat[tid] * x[tid];
            redu[tid] = C_y_un[tid]  * x[128 + tid];
        }
        __syncthreads();
        for (int s2 = 64; s2 > 0; s2 >>= 1) {
            if (tid < s2) { redn[tid] += redn[tid + s2]; redu[tid] += redu[tid + s2]; }
            __syncthreads();
        }
        if (tid == 0) { s_sn = redn[0]; s_su = redu[0]; }
        if (tid < 64) {
            float s = 0.f;
            const float* cr = C_op + tid * 256;
            #pragma unroll 8
            for (int i2 = 0; i2 < 256; i2++) s += cr[i2] * x[256 + i2];
            ph[tid] = s;
        }
        __syncthreads();
        const float sn = s_sn, su = s_su, y = sn + su;
        {
            const int r = tid;
            float s;
            if (r < 128) {
                s = K_nat[r] * y;
                const float* ar = A_nn + r * 128;
                #pragma unroll 8
                for (int j = 0; j < 128; j++) s += ar[j] * x[j];
                const float* br = Bp_nat + r * 64;
                #pragma unroll 8
                for (int c = 0; c < 64; c++) s += br[c] * ph[c];
            } else {
                const int rr = r - 128;
                s = K_un[rr] * su;
                const float* ar = A_uu + rr * 128;
                #pragma unroll 8
                for (int j = 0; j < 128; j++) s += ar[j] * x[128 + j];
                const float* br = Bp_un + rr * 64;
                #pragma unroll 8
                for (int c = 0; c < 64; c++) s += br[c] * ph[c];
            }
            xn[r] = s;
            float so = 0.f;
            const float* ar2 = A_op + r * 256;
            #pragma unroll 8
            for (int j = 0; j < 256; j++) so += ar2[j] * x[256 + j];
            const float* br2 = B_op + r * 32;
            const float* ut  = U + t * 32;
            #pragma unroll 8
            for (int j = 0; j < 32; j++) so += br2[j] * ut[j];
            xn[256 + r] = so;
        }
        __syncthreads();
        if (tid == 0) y_out[t] = y;
        for (int i = tid; i < 512; i += 256) {
            const float v = xn[i];
            x[i] = v;
            const int tt = t + 1;
            if (i < 128)       nat_out[tt * 128 + i] = v;
            else if (i < 256)  un_out[tt * 128 + (i - 128)] = v;
            else               op_out[tt * 256 + (i - 256)] = v;
        }
        __syncthreads();
    }
}

// ---------------------------------------------------------------------------
// k_conv: persistent-ish fp16 mma.sync GEMM. 296 CTAs x 512 threads; each CTA
// owns one 128-col output slice (nb) and processes up to 7 t-tiles of 128 rows.
// B slice (128x384 fp16, 96KB) resident in smem; A double-buffered 2x16KB.
// ---------------------------------------------------------------------------
#define B_BYTES  98304                 // 6 chunks x 16KB
#define A_STAGE  16384
#define SMEM_DYN (B_BYTES + 2 * A_STAGE + 1024)

__device__ __forceinline__ void fill_A(uint32_t sA, int s, int tb, int cc, int tid)
{
    const uint4* Uh4 = (const uint4*)g_Uh;
    const uint32_t sb = sA + s * A_STAGE;
    const int urb = tb - KTAPS + 2 * cc;
    #pragma unroll
    for (int it = 0; it < 2; it++) {
        const int i = it * 512 + tid;          // 0..1023
        const int row = i >> 3, u = i & 7;
        const uint32_t soff = (uint32_t)(row * 128)
                            + (((uint32_t)(u * 16)) ^ ((uint32_t)(row & 7) << 4));
        int ur = urb + row + (u >> 2);
        if (ur > T_TOT - 1) ur = T_TOT - 1;    // feeds only predicated-out t rows
        cp16(sb + soff, Uh4 + ur * 4 + (u & 3));
    }
}

__global__ void __launch_bounds__(512) k_conv(float* __restrict__ out)
{
    extern __shared__ char dsm[];
    const int tid  = threadIdx.x;
    const int wid  = tid >> 5;
    const int lane = tid & 31;
    const int nb   = blockIdx.x;               // output block of 128
    const int by   = blockIdx.y;               // 0..NBY-1
    const int ob   = nb * 128;

    const uint32_t smem_raw = smem_u32(dsm);
    const uint32_t sbase    = (smem_raw + 1023) & ~1023u;
    const uint32_t sB = sbase;
    const uint32_t sA = sbase + B_BYTES;

    // ---- fill resident B slice once (6144 x 16B) ----
    {
        const uint4* Hh4 = (const uint4*)g_Hh;
        #pragma unroll
        for (int it = 0; it < 12; it++) {
            const int i = it * 512 + tid;       // 0..6143
            const int c = i >> 10, rowu = i & 1023;
            const int row = rowu >> 3, u = rowu & 7;
            const uint32_t soff = (uint32_t)(c * 16384 + row * 128)
                                + (((uint32_t)(u * 16)) ^ ((uint32_t)(row & 7) << 4));
            cp16(sB + soff, Hh4 + (ob + row) * (KDIM / 8) + c * 8 + u);
        }
        cp_commit();
    }

    // warp layout: 4x4 warps, warp tile 32(M) x 32(N)
    const int wm = (wid >> 2) * 32;
    const int wn = (wid & 3) * 32;
    const int g  = lane >> 3, r8 = lane & 7;
    const uint32_t xk = (uint32_t)r8 << 4;
    const uint32_t a_row = (uint32_t)(wm + (g & 1) * 8 + r8);
    const uint32_t a_kh  = (uint32_t)((g >> 1) * 16);
    const uint32_t b_rowb = (uint32_t)(wn + (g >> 1) * 8 + r8);
    const uint32_t b_kh  = (uint32_t)((g & 1) * 16);

    // epilogue targets
    float* nat_out = out + T_TOT;
    float* un_out  = nat_out + (T_TOT + 1) * 128;
    float* op_out  = un_out  + (T_TOT + 1) * 128;
    float* base; int stride, col0;
    if      (nb == 0) { base = nat_out; stride = 128; col0 = 0; }
    else if (nb == 1) { base = un_out;  stride = 128; col0 = 0; }
    else if (nb == 2) { base = op_out;  stride = 256; col0 = 0; }
    else              { base = op_out;  stride = 256; col0 = 128; }
    const int rlo = lane >> 2;
    const int cpair = (lane & 3) * 2;

    for (int ii = 0; ii < NI; ii++) {
        const int tt = by + NBY * ii;
        if (tt >= NTT) break;
        const int tb = T0 + 1 + tt * 128;

        float acc[2][4][4];
        #pragma unroll
        for (int mt = 0; mt < 2; mt++)
            #pragma unroll
            for (int nt = 0; nt < 4; nt++)
                #pragma unroll
                for (int q = 0; q < 4; q++) acc[mt][nt][q] = 0.f;

        fill_A(sA, 0, tb, 0, tid); cp_commit();
        fill_A(sA, 1, tb, 1, tid); cp_commit();

        for (int cc = 0; cc < NCHUNK; cc++) {
            const int s = cc & 1;
            if (cc < NCHUNK - 1) asm volatile("cp.async.wait_group 1;" ::: "memory");
            else                 asm volatile("cp.async.wait_group 0;" ::: "memory");
            __syncthreads();

            const uint32_t sAc = sA + s * A_STAGE;
            const uint32_t sBc = sB + cc * 16384;

            #pragma unroll
            for (int ks = 0; ks < 4; ks++) {
                const uint32_t kcol = (uint32_t)(ks * 32);
                uint32_t Ah[2][4], Bh[4][2];
                #pragma unroll
                for (int mt = 0; mt < 2; mt++) {
                    const uint32_t off = (a_row + mt * 16) * 128 + ((kcol + a_kh) ^ xk);
                    ldsm_x4(Ah[mt], sAc + off);
                }
                #pragma unroll
                for (int p = 0; p < 2; p++) {
                    const uint32_t off = (b_rowb + p * 16) * 128 + ((kcol + b_kh) ^ xk);
                    uint32_t th[4];
                    ldsm_x4(th, sBc + off);
                    Bh[2 * p][0] = th[0]; Bh[2 * p][1] = th[1];
                    Bh[2 * p + 1][0] = th[2]; Bh[2 * p + 1][1] = th[3];
                }
                #pragma unroll
                for (int mt = 0; mt < 2; mt++)
                    #pragma unroll
                    for (int nt = 0; nt < 4; nt++)
                        mma16816(acc[mt][nt], Ah[mt], Bh[nt]);
            }
            __syncthreads();
            if (cc + 2 < NCHUNK) { fill_A(sA, s, tb, cc + 2, tid); cp_commit(); }
        }

        // ---- epilogue for this t-tile ----
        #pragma unroll
        for (int mt = 0; mt < 2; mt++) {
            #pragma unroll
            for (int nt = 0; nt < 4; nt++) {
                const int lc = wn + nt * 8 + cpair;
                const int t0 = tb + wm + mt * 16 + rlo;
                float* p0 = base + (size_t)t0 * stride + col0 + lc;
                if (t0 <= T_TOT)
                    *(float2*)p0 = make_float2(acc[mt][nt][0], acc[mt][nt][1]);
                if (t0 + 8 <= T_TOT)
                    *(float2*)(p0 + 8 * stride) = make_float2(acc[mt][nt][2], acc[mt][nt][3]);
            }
        }
    }
}

// ---------------------------------------------------------------------------
// k_y: y[t] = C_y_nat . nat[t] + C_y_un . un[t], t in [T0, T_TOT-1]
// ---------------------------------------------------------------------------
__global__ void k_y(const float* __restrict__ C_y_nat,
                    const float* __restrict__ C_y_un,
                    float* __restrict__ out)
{
    float* y_out = out;
    const float* nat = out + T_TOT;
    const float* un  = nat + (T_TOT + 1) * 128;
    const int warp = threadIdx.x >> 5, lane = threadIdx.x & 31;
    const int t = T0 + (int)blockIdx.x * 8 + warp;
    if (t >= T_TOT) return;
    float s = 0.f;
    #pragma unroll
    for (int c = lane; c < 128; c += 32)
        s += C_y_nat[c] * nat[t * 128 + c] + C_y_un[c] * un[t * 128 + c];
    #pragma unroll
    for (int off = 16; off; off >>= 1) s += __shfl_down_sync(0xffffffffu, s, off);
    if (lane == 0) y_out[t] = s;
}

// ---------------------------------------------------------------------------
extern "C" void kernel_launch(void* const* d_in, const int* in_sizes, int n_in,
                              void* d_out, int out_size)
{
    const float* x_nat0   = (const float*)d_in[0];
    const float* x_unnat0 = (const float*)d_in[1];
    const float* x_opsin0 = (const float*)d_in[2];
    const float* U        = (const float*)d_in[3];
    const float* A_nn     = (const float*)d_in[4];
    const float* K_nat    = (const float*)d_in[5];
    const float* C_y_nat  = (const float*)d_in[6];
    const float* A_uu     = (const float*)d_in[7];
    const float* K_un     = (const float*)d_in[8];
    const float* C_y_un   = (const float*)d_in[9];
    const float* Bp_nat   = (const float*)d_in[10];
    const float* Bp_un    = (const float*)d_in[11];
    const float* A_op     = (const float*)d_in[12];
    const float* B_op     = (const float*)d_in[13];
    const float* C_op     = (const float*)d_in[14];
    float* out = (float*)d_out;

    static bool attr_done = false;
    if (!attr_done) {
        cudaFuncSetAttribute(k_conv, cudaFuncAttributeMaxDynamicSharedMemorySize, SMEM_DYN);
        attr_done = true;
    }

    k_pre<<<161, 256>>>(x_nat0, x_unnat0, x_opsin0, U, A_nn, K_nat, C_y_nat,
                        A_uu, K_un, C_y_un, Bp_nat, Bp_un, A_op, B_op, C_op, out);
    k_conv<<<dim3(4, NBY), 512, SMEM_DYN>>>(out);
    k_y<<<(T_TOT - T0 + 7) / 8, 256>>>(C_y_nat, C_y_un, out);
}

// round 10
// speedup vs baseline: 1.1504x; 1.1504x over previous
#include <cuda_runtime.h>
#include <cuda_fp16.h>
#include <cstdint>

#define T_TOT 65536
#define KTAPS 12              // taps kept; truncation ~0.32^12 ~ 1e-6 rel
#define KDIM  (KTAPS * 32)    // 384
#define T0    24              // exact sequential steps; conv covers t in [T0+1, T_TOT]

// fp16 U and fp16 B = reordered impulse response, row stride KDIM.
__device__ __half g_Uh[T_TOT * 32];
__device__ __half g_Hh[512 * KDIM];   // [o][c], c = (KTAPS-1-k)*32 + j

// ---------------------------------------------------------------------------
__device__ __forceinline__ uint32_t smem_u32(const void* p) {
    uint32_t a;
    asm("{ .reg .u64 t; cvta.to.shared.u64 t, %1; cvt.u32.u64 %0, t; }"
        : "=r"(a) : "l"(p));
    return a;
}
__device__ __forceinline__ void cp16(uint32_t saddr, const void* g) {
    asm volatile("cp.async.cg.shared.global [%0], [%1], 16;" :: "r"(saddr), "l"(g));
}
__device__ __forceinline__ void ldsm_x4(uint32_t* r, uint32_t addr) {
    asm volatile("ldmatrix.sync.aligned.m8n8.x4.shared.b16 {%0,%1,%2,%3}, [%4];"
                 : "=r"(r[0]), "=r"(r[1]), "=r"(r[2]), "=r"(r[3]) : "r"(addr));
}
__device__ __forceinline__ void mma16816(float* d, const uint32_t* a, const uint32_t* b) {
    asm volatile("mma.sync.aligned.m16n8k16.row.col.f32.f16.f16.f32 "
                 "{%0,%1,%2,%3}, {%4,%5,%6,%7}, {%8,%9}, {%0,%1,%2,%3};"
                 : "+f"(d[0]), "+f"(d[1]), "+f"(d[2]), "+f"(d[3])
                 : "r"(a[0]), "r"(a[1]), "r"(a[2]), "r"(a[3]), "r"(b[0]), "r"(b[1]));
}

// ---------------------------------------------------------------------------
// k_preU: U -> fp16 (128 blocks)
// ---------------------------------------------------------------------------
__global__ void __launch_bounds__(256) k_preU(const float* __restrict__ U)
{
    const int base = blockIdx.x * 16384;
    const int tid = threadIdx.x;
    #pragma unroll 4
    for (int p = 0; p < 64; p++) {
        const int idx = base + p * 256 + tid;
        g_Uh[idx] = __float2half(U[idx]);
    }
}

// ---------------------------------------------------------------------------
// k_preH: impulse chains -> fp16 B matrix (32 blocks, one per input col)
// ---------------------------------------------------------------------------
__global__ void __launch_bounds__(256) k_preH(
    const float* __restrict__ A_nn, const float* __restrict__ K_nat,
    const float* __restrict__ C_y_nat, const float* __restrict__ A_uu,
    const float* __restrict__ K_un, const float* __restrict__ C_y_un,
    const float* __restrict__ Bp_nat, const float* __restrict__ Bp_un,
    const float* __restrict__ A_op, const float* __restrict__ B_op,
    const float* __restrict__ C_op)
{
    __shared__ float x[512], xn[512], ph[64], redn[128], redu[128];
    __shared__ float s_sn, s_su;
    const int tid = threadIdx.x;
    const int jcol = blockIdx.x;

    for (int i = tid; i < 512; i += 256)
        x[i] = (i >= 256) ? B_op[(i - 256) * 32 + jcol] : 0.f;
    __syncthreads();
    for (int i = tid; i < 512; i += 256)          // tap k=0
        g_Hh[i * KDIM + (KTAPS - 1) * 32 + jcol] = __float2half(x[i]);
    for (int k = 1; k < KTAPS; k++) {
        if (tid < 128) {
            redn[tid] = C_y_nat[tid] * x[tid];
            redu[tid] = C_y_un[tid]  * x[128 + tid];
        }
        __syncthreads();
        for (int s2 = 64; s2 > 0; s2 >>= 1) {
            if (tid < s2) { redn[tid] += redn[tid + s2]; redu[tid] += redu[tid + s2]; }
            __syncthreads();
        }
        if (tid == 0) { s_sn = redn[0]; s_su = redu[0]; }
        if (tid < 64) {
            float s = 0.f;
            const float* cr = C_op + tid * 256;
            #pragma unroll 8
            for (int i2 = 0; i2 < 256; i2++) s += cr[i2] * x[256 + i2];
            ph[tid] = s;
        }
        __syncthreads();
        const float sn = s_sn, su = s_su;
        {
            const int r = tid;
            float s;
            if (r < 128) {
                s = K_nat[r] * (sn + su);
                const float* ar = A_nn + r * 128;
                #pragma unroll 8
                for (int j = 0; j < 128; j++) s += ar[j] * x[j];
                const float* br = Bp_nat + r * 64;
                #pragma unroll 8
                for (int c = 0; c < 64; c++) s += br[c] * ph[c];
            } else {
                const int rr = r - 128;
                s = K_un[rr] * su;
                const float* ar = A_uu + rr * 128;
                #pragma unroll 8
                for (int j = 0; j < 128; j++) s += ar[j] * x[128 + j];
                const float* br = Bp_un + rr * 64;
                #pragma unroll 8
                for (int c = 0; c < 64; c++) s += br[c] * ph[c];
            }
            xn[r] = s;
            float so = 0.f;
            const float* ar2 = A_op + r * 256;
            #pragma unroll 8
            for (int j = 0; j < 256; j++) so += ar2[j] * x[256 + j];
            xn[256 + r] = so;
        }
        __syncthreads();
        for (int i = tid; i < 512; i += 256) {
            const float v = xn[i];
            x[i] = v;
            g_Hh[i * KDIM + (KTAPS - 1 - k) * 32 + jcol] = __float2half(v);
        }
        __syncthreads();
    }
}

// ---------------------------------------------------------------------------
// k_preX: exact first-T0 simulation (1 block)
// ---------------------------------------------------------------------------
__global__ void __launch_bounds__(256) k_preX(
    const float* __restrict__ x_nat0, const float* __restrict__ x_unnat0,
    const float* __restrict__ x_opsin0, const float* __restrict__ U,
    const float* __restrict__ A_nn, const float* __restrict__ K_nat,
    const float* __restrict__ C_y_nat, const float* __restrict__ A_uu,
    const float* __restrict__ K_un, const float* __restrict__ C_y_un,
    const float* __restrict__ Bp_nat, const float* __restrict__ Bp_un,
    const float* __restrict__ A_op, const float* __restrict__ B_op,
    const float* __restrict__ C_op, float* __restrict__ out)
{
    __shared__ float x[512], xn[512], ph[64], redn[128], redu[128];
    __shared__ float s_sn, s_su;
    const int tid = threadIdx.x;

    float* y_out   = out;
    float* nat_out = out + T_TOT;
    float* un_out  = nat_out + (T_TOT + 1) * 128;
    float* op_out  = un_out  + (T_TOT + 1) * 128;

    for (int i = tid; i < 512; i += 256)
        x[i] = (i < 128) ? x_nat0[i] : (i < 256) ? x_unnat0[i - 128] : x_opsin0[i - 256];
    __syncthreads();
    for (int i = tid; i < 512; i += 256) {
        const float v = x[i];
        if (i < 128)       nat_out[i] = v;
        else if (i < 256)  un_out[i - 128] = v;
        else               op_out[i - 256] = v;
    }
    for (int t = 0; t < T0; t++) {
        if (tid < 128) {
            redn[tid] = C_y_nat[tid] * x[tid];
            redu[tid] = C_y_un[tid]  * x[128 + tid];
        }
        __syncthreads();
        for (int s2 = 64; s2 > 0; s2 >>= 1) {
            if (tid < s2) { redn[tid] += redn[tid + s2]; redu[tid] += redu[tid + s2]; }
            __syncthreads();
        }
        if (tid == 0) { s_sn = redn[0]; s_su = redu[0]; }
        if (tid < 64) {
            float s = 0.f;
            const float* cr = C_op + tid * 256;
            #pragma unroll 8
            for (int i2 = 0; i2 < 256; i2++) s += cr[i2] * x[256 + i2];
            ph[tid] = s;
        }
        __syncthreads();
        const float sn = s_sn, su = s_su, y = sn + su;
        {
            const int r = tid;
            float s;
            if (r < 128) {
                s = K_nat[r] * y;
                const float* ar = A_nn + r * 128;
                #pragma unroll 8
                for (int j = 0; j < 128; j++) s += ar[j] * x[j];
                const float* br = Bp_nat + r * 64;
                #pragma unroll 8
                for (int c = 0; c < 64; c++) s += br[c] * ph[c];
            } else {
                const int rr = r - 128;
                s = K_un[rr] * su;
                const float* ar = A_uu + rr * 128;
                #pragma unroll 8
                for (int j = 0; j < 128; j++) s += ar[j] * x[128 + j];
                const float* br = Bp_un + rr * 64;
                #pragma unroll 8
                for (int c = 0; c < 64; c++) s += br[c] * ph[c];
            }
            xn[r] = s;
            float so = 0.f;
            const float* ar2 = A_op + r * 256;
            #pragma unroll 8
            for (int j = 0; j < 256; j++) so += ar2[j] * x[256 + j];
            const float* br2 = B_op + r * 32;
            const float* ut  = U + t * 32;
            #pragma unroll 8
            for (int j = 0; j < 32; j++) so += br2[j] * ut[j];
            xn[256 + r] = so;
        }
        __syncthreads();
        if (tid == 0) y_out[t] = y;
        for (int i = tid; i < 512; i += 256) {
            const float v = xn[i];
            x[i] = v;
            const int tt = t + 1;
            if (i < 128)       nat_out[tt * 128 + i] = v;
            else if (i < 256)  un_out[tt * 128 + (i - 128)] = v;
            else               op_out[tt * 256 + (i - 256)] = v;
        }
        __syncthreads();
    }
}

// ---------------------------------------------------------------------------
// k_conv: single-phase fp16 mma.sync GEMM exploiting Toeplitz A.
// B (128x384 fp16, 96KB) resident in SW128 chunk tiles; A fragments read
// DIRECTLY from 140 raw U rows (80B padded stride, conflict-free ldmatrix).
// One fill, one barrier, then 24 pure LDSM/MMA k-steps. 2048 CTAs, occ 2.
// ---------------------------------------------------------------------------
#define B_BYTES   98304              // 6 x 16KB SW128 chunk tiles
#define U_ROWS    140
#define U_STRIDE  80                 // 64B data + 16B pad (bank-spread, 16B-mult)
#define U_BYTES   (U_ROWS * U_STRIDE)   // 11200
#define SMEM_DYN  (B_BYTES + U_BYTES + 1088)

__global__ void __launch_bounds__(256, 2) k_conv(float* __restrict__ out)
{
    extern __shared__ char dsm[];
    const int tid  = threadIdx.x;
    const int wid  = tid >> 5;
    const int lane = tid & 31;
    const int nb   = blockIdx.x;                       // output block of 128
    const int tb   = T0 + 1 + (int)blockIdx.y * 128;   // first hist row of tile
    const int ob   = nb * 128;

    const uint32_t smem_raw = smem_u32(dsm);
    const uint32_t sbase    = (smem_raw + 1023) & ~1023u;
    const uint32_t sB = sbase;
    const uint32_t sU = sbase + B_BYTES;

    // ---- fill B (6144 x 16B) : 24 cp16/thread ----
    {
        const uint4* Hh4 = (const uint4*)g_Hh;
        #pragma unroll
        for (int it = 0; it < 24; it++) {
            const int i = it * 256 + tid;            // 0..6143
            const int cc = i >> 10;                  // chunk 0..5
            const int rr = (i >> 3) & 127, u = i & 7;
            const uint32_t soff = (uint32_t)(cc * 16384 + rr * 128)
                                + (((uint32_t)(u * 16)) ^ ((uint32_t)(rr & 7) << 4));
            cp16(sB + soff, Hh4 + (ob + rr) * (KDIM / 8) + cc * 8 + u);
        }
    }
    // ---- fill U rows tb-12 .. tb+127 (140 rows x 4 x 16B) ----
    {
        const uint4* Uh4 = (const uint4*)g_Uh;
        #pragma unroll
        for (int it = 0; it < 3; it++) {
            const int i = it * 256 + tid;            // 0..767 (need 560)
            if (i < U_ROWS * 4) {
                const int r = i >> 2, s = i & 3;
                int ur = tb - KTAPS + r;
                if (ur > T_TOT - 1) ur = T_TOT - 1;  // feeds only predicated-out rows
                cp16(sU + (uint32_t)(r * U_STRIDE + s * 16), Uh4 + ur * 4 + s);
            }
        }
    }
    asm volatile("cp.async.commit_group;" ::: "memory");
    asm volatile("cp.async.wait_group 0;" ::: "memory");
    __syncthreads();

    // warp layout: 2x4 warps, warp tile 64(M) x 32(N)
    const int wm = (wid >> 2) * 64;
    const int wn = (wid & 3) * 32;
    const int g  = lane >> 3, r8 = lane & 7;
    const uint32_t xk = (uint32_t)r8 << 4;
    // A from raw U rows: row = wm + (g&1)*8 + r8 (+ mt*16 + kk/2), col half g>>1
    const uint32_t a_row0 = (uint32_t)(wm + (g & 1) * 8 + r8);
    const uint32_t a_cb   = (uint32_t)((g >> 1) * 16);
    // B from SW128 tiles (as R5)
    const uint32_t b_row = (uint32_t)(wn + (g >> 1) * 8 + r8);
    const uint32_t b_kh  = (uint32_t)((g & 1) * 16);

    float acc[4][4][4];
    #pragma unroll
    for (int mt = 0; mt < 4; mt++)
        #pragma unroll
        for (int nt = 0; nt < 4; nt++)
            #pragma unroll
            for (int q = 0; q < 4; q++) acc[mt][nt][q] = 0.f;

    #pragma unroll 4
    for (int kk = 0; kk < 24; kk++) {                  // k16 steps
        const uint32_t aoff = sU + (a_row0 + (kk >> 1)) * U_STRIDE
                            + a_cb + (uint32_t)((kk & 1) * 32);
        uint32_t Ah[4][4], Bh[4][2];
        #pragma unroll
        for (int mt = 0; mt < 4; mt++)
            ldsm_x4(Ah[mt], aoff + mt * 16 * U_STRIDE);
        {
            const uint32_t sBc = sB + (kk >> 2) * 16384;
            const uint32_t kcol = (uint32_t)((kk & 3) * 32);
            #pragma unroll
            for (int p = 0; p < 2; p++) {
                uint32_t th[4];
                ldsm_x4(th, sBc + (b_row + p * 16) * 128 + ((kcol + b_kh) ^ xk));
                Bh[2 * p][0] = th[0]; Bh[2 * p][1] = th[1];
                Bh[2 * p + 1][0] = th[2]; Bh[2 * p + 1][1] = th[3];
            }
        }
        #pragma unroll
        for (int mt = 0; mt < 4; mt++)
            #pragma unroll
            for (int nt = 0; nt < 4; nt++)
                mma16816(acc[mt][nt], Ah[mt], Bh[nt]);
    }

    // ---- epilogue ----
    float* nat_out = out + T_TOT;
    float* un_out  = nat_out + (T_TOT + 1) * 128;
    float* op_out  = un_out  + (T_TOT + 1) * 128;
    float* base; int stride, col0;
    if      (nb == 0) { base = nat_out; stride = 128; col0 = 0; }
    else if (nb == 1) { base = un_out;  stride = 128; col0 = 0; }
    else if (nb == 2) { base = op_out;  stride = 256; col0 = 0; }
    else              { base = op_out;  stride = 256; col0 = 128; }

    const int rlo = lane >> 2;
    const int cpair = (lane & 3) * 2;
    #pragma unroll
    for (int mt = 0; mt < 4; mt++) {
        #pragma unroll
        for (int nt = 0; nt < 4; nt++) {
            const int lc = wn + nt * 8 + cpair;
            const int t0 = tb + wm + mt * 16 + rlo;
            float* p0 = base + (size_t)t0 * stride + col0 + lc;
            if (t0 <= T_TOT)
                *(float2*)p0 = make_float2(acc[mt][nt][0], acc[mt][nt][1]);
            if (t0 + 8 <= T_TOT)
                *(float2*)(p0 + 8 * stride) = make_float2(acc[mt][nt][2], acc[mt][nt][3]);
        }
    }
}

// ---------------------------------------------------------------------------
// k_y: y[t] = C_y_nat . nat[t] + C_y_un . un[t], t in [T0, T_TOT-1]
// ---------------------------------------------------------------------------
__global__ void k_y(const float* __restrict__ C_y_nat,
                    const float* __restrict__ C_y_un,
                    float* __restrict__ out)
{
    float* y_out = out;
    const float* nat = out + T_TOT;
    const float* un  = nat + (T_TOT + 1) * 128;
    const int warp = threadIdx.x >> 5, lane = threadIdx.x & 31;
    const int t = T0 + (int)blockIdx.x * 8 + warp;
    if (t >= T_TOT) return;
    float s = 0.f;
    #pragma unroll
    for (int c = lane; c < 128; c += 32)
        s += C_y_nat[c] * nat[t * 128 + c] + C_y_un[c] * un[t * 128 + c];
    #pragma unroll
    for (int off = 16; off; off >>= 1) s += __shfl_down_sync(0xffffffffu, s, off);
    if (lane == 0) y_out[t] = s;
}

// ---------------------------------------------------------------------------
extern "C" void kernel_launch(void* const* d_in, const int* in_sizes, int n_in,
                              void* d_out, int out_size)
{
    const float* x_nat0   = (const float*)d_in[0];
    const float* x_unnat0 = (const float*)d_in[1];
    const float* x_opsin0 = (const float*)d_in[2];
    const float* U        = (const float*)d_in[3];
    const float* A_nn     = (const float*)d_in[4];
    const float* K_nat    = (const float*)d_in[5];
    const float* C_y_nat  = (const float*)d_in[6];
    const float* A_uu     = (const float*)d_in[7];
    const float* K_un     = (const float*)d_in[8];
    const float* C_y_un   = (const float*)d_in[9];
    const float* Bp_nat   = (const float*)d_in[10];
    const float* Bp_un    = (const float*)d_in[11];
    const float* A_op     = (const float*)d_in[12];
    const float* B_op     = (const float*)d_in[13];
    const float* C_op     = (const float*)d_in[14];
    float* out = (float*)d_out;

    cudaFuncSetAttribute(k_conv, cudaFuncAttributeMaxDynamicSharedMemorySize, SMEM_DYN);

    k_preU<<<128, 256>>>(U);
    k_preH<<<32, 256>>>(A_nn, K_nat, C_y_nat, A_uu, K_un, C_y_un,
                        Bp_nat, Bp_un, A_op, B_op, C_op);
    k_preX<<<1, 256>>>(x_nat0, x_unnat0, x_opsin0, U, A_nn, K_nat, C_y_nat,
                       A_uu, K_un, C_y_un, Bp_nat, Bp_un, A_op, B_op, C_op, out);
    k_conv<<<dim3(4, 512), 256, SMEM_DYN>>>(out);
    k_y<<<(T_TOT - T0 + 7) / 8, 256>>>(C_y_nat, C_y_un, out);
}